// round 1
// baseline (speedup 1.0000x reference)
#include <cuda_runtime.h>
#include <math.h>

// Problem constants
#define NTOK (8*8192)        // 65536 tokens
#define DIMC 512
#define NSLOT 64
#define CHUNKT 64
#define NCHUNK (NTOK/CHUNKT) // 1024

// ---------------- scratch (device globals; no allocation allowed) ----------------
__device__ float g_k [(size_t)NTOK*DIMC];
__device__ float g_q [(size_t)NTOK*DIMC];
__device__ float g_v [(size_t)NTOK*DIMC];
__device__ float g_ret[(size_t)NTOK*DIMC];
__device__ float g_ln [(size_t)NTOK*DIMC];
__device__ float g_ww [(size_t)NTOK*NSLOT];
__device__ float g_rw [(size_t)NTOK*NSLOT];

// ---------------- GEMM: C[M,N] = A[M,K] @ W[K,N] + bias (+ resid) ----------------
// 128x128 tile, BK=16, 256 threads, 8x8 microtile per thread.
#define BM 128
#define BN 128
#define BKG 16

__global__ __launch_bounds__(256) void gemm_bias(
    const float* __restrict__ A, const float* __restrict__ W,
    const float* __restrict__ bias, const float* __restrict__ resid,
    float* __restrict__ C, int M, int N, int K)
{
    __shared__ float As[BKG][BM+4];   // k-major, padded (conflict-free transposed stores)
    __shared__ float Bs[BKG][BN];
    const int tid = threadIdx.x;
    const int tx = tid & 15, ty = tid >> 4;
    const int m0 = blockIdx.y * BM, n0 = blockIdx.x * BN;
    const int arow = tid >> 2, avec = (tid & 3) << 2;
    const int brow = tid >> 5, bvec = (tid & 31) << 2;
    float acc[8][8] = {};

    for (int k0 = 0; k0 < K; k0 += BKG) {
        #pragma unroll
        for (int i = 0; i < 2; i++) {
            int r = arow + i*64;
            float4 a = *(const float4*)(A + (size_t)(m0+r)*K + k0 + avec);
            As[avec+0][r] = a.x; As[avec+1][r] = a.y;
            As[avec+2][r] = a.z; As[avec+3][r] = a.w;
        }
        #pragma unroll
        for (int i = 0; i < 2; i++) {
            int r = brow + i*8;
            *(float4*)&Bs[r][bvec] = *(const float4*)(W + (size_t)(k0+r)*N + n0 + bvec);
        }
        __syncthreads();
        #pragma unroll
        for (int kk = 0; kk < BKG; kk++) {
            float a[8], bb[8];
            *(float4*)&a[0]  = *(float4*)&As[kk][ty*8];
            *(float4*)&a[4]  = *(float4*)&As[kk][ty*8+4];
            *(float4*)&bb[0] = *(float4*)&Bs[kk][tx*8];
            *(float4*)&bb[4] = *(float4*)&Bs[kk][tx*8+4];
            #pragma unroll
            for (int i = 0; i < 8; i++)
                #pragma unroll
                for (int j = 0; j < 8; j++)
                    acc[i][j] = fmaf(a[i], bb[j], acc[i][j]);
        }
        __syncthreads();
    }

    float bn[8];
    *(float4*)&bn[0] = *(const float4*)(bias + n0 + tx*8);
    *(float4*)&bn[4] = *(const float4*)(bias + n0 + tx*8 + 4);
    #pragma unroll
    for (int i = 0; i < 8; i++) {
        size_t off = (size_t)(m0 + ty*8 + i)*N + n0 + tx*8;
        float4 r0, r1;
        r0.x = acc[i][0]+bn[0]; r0.y = acc[i][1]+bn[1];
        r0.z = acc[i][2]+bn[2]; r0.w = acc[i][3]+bn[3];
        r1.x = acc[i][4]+bn[4]; r1.y = acc[i][5]+bn[5];
        r1.z = acc[i][6]+bn[6]; r1.w = acc[i][7]+bn[7];
        if (resid) {
            float4 e0 = *(const float4*)(resid + off);
            float4 e1 = *(const float4*)(resid + off + 4);
            r0.x += e0.x; r0.y += e0.y; r0.z += e0.z; r0.w += e0.w;
            r1.x += e1.x; r1.y += e1.y; r1.z += e1.z; r1.w += e1.w;
        }
        *(float4*)(C + off)     = r0;
        *(float4*)(C + off + 4) = r1;
    }
}

// -------- slot logits + softmax: Wout[tok,s] = softmax_s( X[tok,:] . SK[s,:] * scale ) --------
// Block handles 64 tokens x 64 slots. NT-gemm over K=512, fused row softmax.
__global__ __launch_bounds__(256) void slot_softmax(
    const float* __restrict__ X, const float* __restrict__ SK,
    const float* __restrict__ scale_p, float* __restrict__ Wout)
{
    __shared__ float Xs[16][68];
    __shared__ float Ss[16][68];
    __shared__ float L[64][65];
    __shared__ float rinv[64];
    const int tid = threadIdx.x;
    const int tx = tid & 15, ty = tid >> 4;
    const int tok0 = blockIdx.x * 64;
    const int row = tid >> 2, vec = (tid & 3) << 2;
    float acc[4][4] = {};

    for (int k0 = 0; k0 < DIMC; k0 += 16) {
        float4 xa = *(const float4*)(X + (size_t)(tok0+row)*DIMC + k0 + vec);
        Xs[vec+0][row]=xa.x; Xs[vec+1][row]=xa.y; Xs[vec+2][row]=xa.z; Xs[vec+3][row]=xa.w;
        float4 sa = *(const float4*)(SK + (size_t)row*DIMC + k0 + vec);
        Ss[vec+0][row]=sa.x; Ss[vec+1][row]=sa.y; Ss[vec+2][row]=sa.z; Ss[vec+3][row]=sa.w;
        __syncthreads();
        #pragma unroll
        for (int kk = 0; kk < 16; kk++) {
            float a[4], bb[4];
            *(float4*)&a[0]  = *(float4*)&Xs[kk][ty*4];
            *(float4*)&bb[0] = *(float4*)&Ss[kk][tx*4];
            #pragma unroll
            for (int i = 0; i < 4; i++)
                #pragma unroll
                for (int j = 0; j < 4; j++)
                    acc[i][j] = fmaf(a[i], bb[j], acc[i][j]);
        }
        __syncthreads();
    }

    const float sc = scale_p[0];
    #pragma unroll
    for (int i = 0; i < 4; i++)
        #pragma unroll
        for (int j = 0; j < 4; j++)
            L[ty*4+i][tx*4+j] = acc[i][j] * sc;
    __syncthreads();

    if (tid < 64) {
        float mx = -1e30f;
        #pragma unroll 8
        for (int s = 0; s < 64; s++) mx = fmaxf(mx, L[tid][s]);
        float sum = 0.f;
        #pragma unroll 8
        for (int s = 0; s < 64; s++) { float e = expf(L[tid][s]-mx); L[tid][s] = e; sum += e; }
        rinv[tid] = 1.f / sum;
    }
    __syncthreads();

    #pragma unroll
    for (int i = 0; i < 4; i++) {
        int t = ty*4 + i;
        float rv = rinv[t];
        float4 w;
        w.x = L[t][tx*4+0]*rv; w.y = L[t][tx*4+1]*rv;
        w.z = L[t][tx*4+2]*rv; w.w = L[t][tx*4+3]*rv;
        *(float4*)(Wout + (size_t)(tok0+t)*NSLOT + tx*4) = w;
    }
}

// -------- per-chunk: A = rw @ ww^T (causal-masked), retrieved = A @ v --------
__global__ __launch_bounds__(256) void chunk_attn(
    const float* __restrict__ rw, const float* __restrict__ ww,
    const float* __restrict__ v, float* __restrict__ ret)
{
    extern __shared__ float cbuf[];
    float* RW = cbuf;              // [64][65]
    float* WW = cbuf + 64*65;      // [64][65]
    float* Vs = cbuf + 2*64*65;    // [64][64]
    const int tid = threadIdx.x;
    const int tx = tid & 15, ty = tid >> 4;
    const int c0 = blockIdx.x * CHUNKT;

    for (int i = tid; i < 64*64; i += 256) {
        int r = i >> 6, s = i & 63;
        RW[r*65+s] = rw[(size_t)(c0+r)*NSLOT + s];
        WW[r*65+s] = ww[(size_t)(c0+r)*NSLOT + s];
    }
    __syncthreads();

    float a4[4][4] = {};
    for (int s = 0; s < 64; s++) {
        float ra[4], wb[4];
        #pragma unroll
        for (int i = 0; i < 4; i++) ra[i] = RW[(ty*4+i)*65 + s];
        #pragma unroll
        for (int j = 0; j < 4; j++) wb[j] = WW[(tx*4+j)*65 + s];
        #pragma unroll
        for (int i = 0; i < 4; i++)
            #pragma unroll
            for (int j = 0; j < 4; j++)
                a4[i][j] = fmaf(ra[i], wb[j], a4[i][j]);
    }
    __syncthreads();

    // causal mask, A aliases RW
    #pragma unroll
    for (int i = 0; i < 4; i++) {
        int t = ty*4 + i;
        #pragma unroll
        for (int j = 0; j < 4; j++) {
            int u = tx*4 + j;
            RW[t*65+u] = (u <= t) ? a4[i][j] : 0.f;
        }
    }
    __syncthreads();
    float* Amat = RW;

    for (int d0 = 0; d0 < DIMC; d0 += 64) {
        for (int i = tid; i < 1024; i += 256) {
            int r = i >> 4, c = (i & 15) << 2;
            *(float4*)&Vs[r*64+c] = *(const float4*)(v + (size_t)(c0+r)*DIMC + d0 + c);
        }
        __syncthreads();
        float racc[4][4] = {};
        for (int u = 0; u < 64; u++) {
            float av[4];
            #pragma unroll
            for (int i = 0; i < 4; i++) av[i] = Amat[(ty*4+i)*65 + u];
            float4 vv = *(float4*)&Vs[u*64 + tx*4];
            #pragma unroll
            for (int i = 0; i < 4; i++) {
                racc[i][0] = fmaf(av[i], vv.x, racc[i][0]);
                racc[i][1] = fmaf(av[i], vv.y, racc[i][1]);
                racc[i][2] = fmaf(av[i], vv.z, racc[i][2]);
                racc[i][3] = fmaf(av[i], vv.w, racc[i][3]);
            }
        }
        #pragma unroll
        for (int i = 0; i < 4; i++) {
            float4 o; o.x = racc[i][0]; o.y = racc[i][1]; o.z = racc[i][2]; o.w = racc[i][3];
            *(float4*)(ret + (size_t)(c0+ty*4+i)*DIMC + d0 + tx*4) = o;
        }
        __syncthreads();
    }
}

// -------- LayerNorm over last dim (512) --------
__global__ __launch_bounds__(128) void ln_kernel(
    const float* __restrict__ X, const float* __restrict__ g,
    const float* __restrict__ b, float* __restrict__ Y)
{
    const int row = blockIdx.x;
    const int tid = threadIdx.x;
    float4 xv = *(const float4*)(X + (size_t)row*DIMC + tid*4);
    float s  = xv.x + xv.y + xv.z + xv.w;
    float ss = fmaf(xv.x,xv.x, fmaf(xv.y,xv.y, fmaf(xv.z,xv.z, xv.w*xv.w)));
    #pragma unroll
    for (int o = 16; o > 0; o >>= 1) {
        s  += __shfl_xor_sync(0xffffffffu, s,  o);
        ss += __shfl_xor_sync(0xffffffffu, ss, o);
    }
    __shared__ float sh_s[4], sh_ss[4];
    int w = tid >> 5;
    if ((tid & 31) == 0) { sh_s[w] = s; sh_ss[w] = ss; }
    __syncthreads();
    s  = sh_s[0] + sh_s[1] + sh_s[2] + sh_s[3];
    ss = sh_ss[0] + sh_ss[1] + sh_ss[2] + sh_ss[3];
    const float mu  = s * (1.f/512.f);
    const float var = ss * (1.f/512.f) - mu*mu;
    const float r   = rsqrtf(var + 1e-5f);
    float4 gv = *(const float4*)(g + tid*4);
    float4 bv = *(const float4*)(b + tid*4);
    float4 y;
    y.x = (xv.x - mu)*r*gv.x + bv.x;
    y.y = (xv.y - mu)*r*gv.y + bv.y;
    y.z = (xv.z - mu)*r*gv.z + bv.z;
    y.w = (xv.w - mu)*r*gv.w + bv.w;
    *(float4*)(Y + (size_t)row*DIMC + tid*4) = y;
}

// ---------------- launch ----------------
extern "C" void kernel_launch(void* const* d_in, const int* in_sizes, int n_in,
                              void* d_out, int out_size)
{
    (void)in_sizes; (void)n_in; (void)out_size;
    const float* x   = (const float*)d_in[0];
    const float* sk  = (const float*)d_in[1];
    const float* Wk  = (const float*)d_in[2];
    const float* bk  = (const float*)d_in[3];
    const float* Wq  = (const float*)d_in[4];
    const float* bq  = (const float*)d_in[5];
    const float* Wv  = (const float*)d_in[6];
    const float* bv  = (const float*)d_in[7];
    const float* sc  = (const float*)d_in[8];
    const float* lng = (const float*)d_in[9];
    const float* lnb = (const float*)d_in[10];
    const float* Wo  = (const float*)d_in[11];
    const float* bo  = (const float*)d_in[12];
    float* out = (float*)d_out;

    float *kp,*qp,*vp,*retp,*lnp,*wwp,*rwp;
    cudaGetSymbolAddress((void**)&kp,  g_k);
    cudaGetSymbolAddress((void**)&qp,  g_q);
    cudaGetSymbolAddress((void**)&vp,  g_v);
    cudaGetSymbolAddress((void**)&retp,g_ret);
    cudaGetSymbolAddress((void**)&lnp, g_ln);
    cudaGetSymbolAddress((void**)&wwp, g_ww);
    cudaGetSymbolAddress((void**)&rwp, g_rw);

    const int chunk_smem = (2*64*65 + 64*64) * (int)sizeof(float); // 49664 B
    cudaFuncSetAttribute(chunk_attn, cudaFuncAttributeMaxDynamicSharedMemorySize, chunk_smem);

    dim3 gg(DIMC/BN, NTOK/BM); // (4, 512)
    gemm_bias<<<gg, 256>>>(x, Wk, bk, nullptr, kp, NTOK, DIMC, DIMC);
    gemm_bias<<<gg, 256>>>(x, Wq, bq, nullptr, qp, NTOK, DIMC, DIMC);
    gemm_bias<<<gg, 256>>>(x, Wv, bv, nullptr, vp, NTOK, DIMC, DIMC);

    slot_softmax<<<NTOK/64, 256>>>(kp, sk, sc, wwp);
    slot_softmax<<<NTOK/64, 256>>>(qp, sk, sc, rwp);

    chunk_attn<<<NCHUNK, 256, chunk_smem>>>(rwp, wwp, vp, retp);

    ln_kernel<<<NTOK, 128>>>(retp, lng, lnb, lnp);

    gemm_bias<<<gg, 256>>>(lnp, Wo, bo, x, out, NTOK, DIMC, DIMC);
}

// round 2
// speedup vs baseline: 2.1333x; 2.1333x over previous
#include <cuda_runtime.h>
#include <math.h>

// Problem constants
#define NTOK (8*8192)        // 65536 tokens
#define DIMC 512
#define NSLOT 64
#define CHUNKT 64
#define NCHUNK (NTOK/CHUNKT) // 1024

// ---------------- scratch (device globals; no allocation allowed) ----------------
__device__ float g_k [(size_t)NTOK*DIMC];
__device__ float g_q [(size_t)NTOK*DIMC];
__device__ float g_v [(size_t)NTOK*DIMC];
__device__ float g_ret[(size_t)NTOK*DIMC];
__device__ float g_ln [(size_t)NTOK*DIMC];
__device__ float g_ww [(size_t)NTOK*NSLOT];
__device__ float g_rw [(size_t)NTOK*NSLOT];

// ---------------- TF32 helpers ----------------
__device__ __forceinline__ unsigned f2tf32(float x) {
    unsigned r;
    asm("cvt.rna.tf32.f32 %0, %1;" : "=r"(r) : "f"(x));
    return r;
}

__device__ __forceinline__ void mma_tf32(float c[4],
    unsigned a0, unsigned a1, unsigned a2, unsigned a3,
    unsigned b0, unsigned b1)
{
    asm volatile(
        "mma.sync.aligned.m16n8k8.row.col.f32.tf32.tf32.f32 "
        "{%0,%1,%2,%3},{%4,%5,%6,%7},{%8,%9},{%0,%1,%2,%3};"
        : "+f"(c[0]), "+f"(c[1]), "+f"(c[2]), "+f"(c[3])
        : "r"(a0), "r"(a1), "r"(a2), "r"(a3), "r"(b0), "r"(b1));
}

// ---------------- TF32 tensor-core GEMM: C[M,N] = A[M,K] @ W[K,N] + bias (+resid) ----------------
// 128x128 tile, BK=32, 256 threads = 8 warps (2 m x 4 n), warp tile 64x32.
#define TBM 128
#define TBN 128
#define TBK 32
#define AS_STRIDE 36    // floats; bank = (4*r + c) % 32 -> conflict-free frag loads
#define BS_STRIDE 136   // floats; bank = (8*k + n) % 32 -> conflict-free frag loads

__global__ __launch_bounds__(256) void gemm_tf32(
    const float* __restrict__ A, const float* __restrict__ W,
    const float* __restrict__ bias, const float* __restrict__ resid,
    float* __restrict__ C, int M, int N, int K)
{
    __shared__ unsigned As[TBM][AS_STRIDE];
    __shared__ unsigned Bs[TBK][BS_STRIDE];

    const int tid  = threadIdx.x;
    const int lane = tid & 31;
    const int wid  = tid >> 5;
    const int warp_m = wid >> 2;   // 0..1 -> 64-row slab
    const int warp_n = wid & 3;    // 0..3 -> 32-col slab
    const int gid = lane >> 2;     // 0..7
    const int tig = lane & 3;      // 0..3
    const int m0 = blockIdx.y * TBM;
    const int n0 = blockIdx.x * TBN;

    // global staging indices
    const int a_row = tid >> 1;            // 0..127
    const int a_col = (tid & 1) * 16;      // 0/16
    const int b_row = tid >> 3;            // 0..31
    const int b_col = (tid & 7) * 16;      // 0..112

    float acc[4][4][4] = {};               // [m-tile][n-tile][frag]

    for (int k0 = 0; k0 < K; k0 += TBK) {
        // ---- stage A tile (convert to tf32-RN on store) ----
        const float* ag = A + (size_t)(m0 + a_row) * K + k0 + a_col;
        #pragma unroll
        for (int v = 0; v < 4; v++) {
            float4 t = *(const float4*)(ag + v * 4);
            uint4 u;
            u.x = f2tf32(t.x); u.y = f2tf32(t.y);
            u.z = f2tf32(t.z); u.w = f2tf32(t.w);
            *(uint4*)&As[a_row][a_col + v * 4] = u;
        }
        // ---- stage B tile ----
        const float* bg = W + (size_t)(k0 + b_row) * N + n0 + b_col;
        #pragma unroll
        for (int v = 0; v < 4; v++) {
            float4 t = *(const float4*)(bg + v * 4);
            uint4 u;
            u.x = f2tf32(t.x); u.y = f2tf32(t.y);
            u.z = f2tf32(t.z); u.w = f2tf32(t.w);
            *(uint4*)&Bs[b_row][b_col + v * 4] = u;
        }
        __syncthreads();

        // ---- compute: 4 k-steps of 8 ----
        #pragma unroll
        for (int kk = 0; kk < TBK; kk += 8) {
            unsigned af[4][4];
            #pragma unroll
            for (int mt = 0; mt < 4; mt++) {
                int r = warp_m * 64 + mt * 16 + gid;
                af[mt][0] = As[r    ][kk + tig    ];
                af[mt][1] = As[r + 8][kk + tig    ];
                af[mt][2] = As[r    ][kk + tig + 4];
                af[mt][3] = As[r + 8][kk + tig + 4];
            }
            unsigned bf[4][2];
            #pragma unroll
            for (int nt = 0; nt < 4; nt++) {
                int c = warp_n * 32 + nt * 8 + gid;
                bf[nt][0] = Bs[kk + tig    ][c];
                bf[nt][1] = Bs[kk + tig + 4][c];
            }
            #pragma unroll
            for (int mt = 0; mt < 4; mt++)
                #pragma unroll
                for (int nt = 0; nt < 4; nt++)
                    mma_tf32(acc[mt][nt], af[mt][0], af[mt][1], af[mt][2], af[mt][3],
                             bf[nt][0], bf[nt][1]);
        }
        __syncthreads();
    }

    // ---- epilogue: +bias (+resid), write float2 pairs ----
    #pragma unroll
    for (int nt = 0; nt < 4; nt++) {
        int cb = n0 + warp_n * 32 + nt * 8 + 2 * tig;
        float b0 = bias[cb], b1 = bias[cb + 1];
        #pragma unroll
        for (int mt = 0; mt < 4; mt++) {
            int r0 = m0 + warp_m * 64 + mt * 16 + gid;
            int r1 = r0 + 8;
            size_t off0 = (size_t)r0 * N + cb;
            size_t off1 = (size_t)r1 * N + cb;
            float2 o0, o1;
            o0.x = acc[mt][nt][0] + b0; o0.y = acc[mt][nt][1] + b1;
            o1.x = acc[mt][nt][2] + b0; o1.y = acc[mt][nt][3] + b1;
            if (resid) {
                float2 e0 = *(const float2*)(resid + off0);
                float2 e1 = *(const float2*)(resid + off1);
                o0.x += e0.x; o0.y += e0.y;
                o1.x += e1.x; o1.y += e1.y;
            }
            *(float2*)(C + off0) = o0;
            *(float2*)(C + off1) = o1;
        }
    }
}

// -------- slot logits + softmax: Wout[tok,s] = softmax_s( X[tok,:] . SK[s,:] * scale ) --------
__global__ __launch_bounds__(256) void slot_softmax(
    const float* __restrict__ X, const float* __restrict__ SK,
    const float* __restrict__ scale_p, float* __restrict__ Wout)
{
    __shared__ float Xs[16][68];
    __shared__ float Ss[16][68];
    __shared__ float L[64][65];
    __shared__ float rinv[64];
    const int tid = threadIdx.x;
    const int tx = tid & 15, ty = tid >> 4;
    const int tok0 = blockIdx.x * 64;
    const int row = tid >> 2, vec = (tid & 3) << 2;
    float acc[4][4] = {};

    for (int k0 = 0; k0 < DIMC; k0 += 16) {
        float4 xa = *(const float4*)(X + (size_t)(tok0+row)*DIMC + k0 + vec);
        Xs[vec+0][row]=xa.x; Xs[vec+1][row]=xa.y; Xs[vec+2][row]=xa.z; Xs[vec+3][row]=xa.w;
        float4 sa = *(const float4*)(SK + (size_t)row*DIMC + k0 + vec);
        Ss[vec+0][row]=sa.x; Ss[vec+1][row]=sa.y; Ss[vec+2][row]=sa.z; Ss[vec+3][row]=sa.w;
        __syncthreads();
        #pragma unroll
        for (int kk = 0; kk < 16; kk++) {
            float a[4], bb[4];
            *(float4*)&a[0]  = *(float4*)&Xs[kk][ty*4];
            *(float4*)&bb[0] = *(float4*)&Ss[kk][tx*4];
            #pragma unroll
            for (int i = 0; i < 4; i++)
                #pragma unroll
                for (int j = 0; j < 4; j++)
                    acc[i][j] = fmaf(a[i], bb[j], acc[i][j]);
        }
        __syncthreads();
    }

    const float sc = scale_p[0];
    #pragma unroll
    for (int i = 0; i < 4; i++)
        #pragma unroll
        for (int j = 0; j < 4; j++)
            L[ty*4+i][tx*4+j] = acc[i][j] * sc;
    __syncthreads();

    if (tid < 64) {
        float mx = -1e30f;
        #pragma unroll 8
        for (int s = 0; s < 64; s++) mx = fmaxf(mx, L[tid][s]);
        float sum = 0.f;
        #pragma unroll 8
        for (int s = 0; s < 64; s++) { float e = expf(L[tid][s]-mx); L[tid][s] = e; sum += e; }
        rinv[tid] = 1.f / sum;
    }
    __syncthreads();

    #pragma unroll
    for (int i = 0; i < 4; i++) {
        int t = ty*4 + i;
        float rv = rinv[t];
        float4 w;
        w.x = L[t][tx*4+0]*rv; w.y = L[t][tx*4+1]*rv;
        w.z = L[t][tx*4+2]*rv; w.w = L[t][tx*4+3]*rv;
        *(float4*)(Wout + (size_t)(tok0+t)*NSLOT + tx*4) = w;
    }
}

// -------- per-chunk: A = rw @ ww^T (causal-masked), retrieved = A @ v --------
__global__ __launch_bounds__(256) void chunk_attn(
    const float* __restrict__ rw, const float* __restrict__ ww,
    const float* __restrict__ v, float* __restrict__ ret)
{
    extern __shared__ float cbuf[];
    float* RW = cbuf;              // [64][65]
    float* WW = cbuf + 64*65;      // [64][65]
    float* Vs = cbuf + 2*64*65;    // [64][64]
    const int tid = threadIdx.x;
    const int tx = tid & 15, ty = tid >> 4;
    const int c0 = blockIdx.x * CHUNKT;

    for (int i = tid; i < 64*64; i += 256) {
        int r = i >> 6, s = i & 63;
        RW[r*65+s] = rw[(size_t)(c0+r)*NSLOT + s];
        WW[r*65+s] = ww[(size_t)(c0+r)*NSLOT + s];
    }
    __syncthreads();

    float a4[4][4] = {};
    for (int s = 0; s < 64; s++) {
        float ra[4], wb[4];
        #pragma unroll
        for (int i = 0; i < 4; i++) ra[i] = RW[(ty*4+i)*65 + s];
        #pragma unroll
        for (int j = 0; j < 4; j++) wb[j] = WW[(tx*4+j)*65 + s];
        #pragma unroll
        for (int i = 0; i < 4; i++)
            #pragma unroll
            for (int j = 0; j < 4; j++)
                a4[i][j] = fmaf(ra[i], wb[j], a4[i][j]);
    }
    __syncthreads();

    #pragma unroll
    for (int i = 0; i < 4; i++) {
        int t = ty*4 + i;
        #pragma unroll
        for (int j = 0; j < 4; j++) {
            int u = tx*4 + j;
            RW[t*65+u] = (u <= t) ? a4[i][j] : 0.f;
        }
    }
    __syncthreads();
    float* Amat = RW;

    for (int d0 = 0; d0 < DIMC; d0 += 64) {
        for (int i = tid; i < 1024; i += 256) {
            int r = i >> 4, c = (i & 15) << 2;
            *(float4*)&Vs[r*64+c] = *(const float4*)(v + (size_t)(c0+r)*DIMC + d0 + c);
        }
        __syncthreads();
        float racc[4][4] = {};
        for (int u = 0; u < 64; u++) {
            float av[4];
            #pragma unroll
            for (int i = 0; i < 4; i++) av[i] = Amat[(ty*4+i)*65 + u];
            float4 vv = *(float4*)&Vs[u*64 + tx*4];
            #pragma unroll
            for (int i = 0; i < 4; i++) {
                racc[i][0] = fmaf(av[i], vv.x, racc[i][0]);
                racc[i][1] = fmaf(av[i], vv.y, racc[i][1]);
                racc[i][2] = fmaf(av[i], vv.z, racc[i][2]);
                racc[i][3] = fmaf(av[i], vv.w, racc[i][3]);
            }
        }
        #pragma unroll
        for (int i = 0; i < 4; i++) {
            float4 o; o.x = racc[i][0]; o.y = racc[i][1]; o.z = racc[i][2]; o.w = racc[i][3];
            *(float4*)(ret + (size_t)(c0+ty*4+i)*DIMC + d0 + tx*4) = o;
        }
        __syncthreads();
    }
}

// -------- LayerNorm over last dim (512) --------
__global__ __launch_bounds__(128) void ln_kernel(
    const float* __restrict__ X, const float* __restrict__ g,
    const float* __restrict__ b, float* __restrict__ Y)
{
    const int row = blockIdx.x;
    const int tid = threadIdx.x;
    float4 xv = *(const float4*)(X + (size_t)row*DIMC + tid*4);
    float s  = xv.x + xv.y + xv.z + xv.w;
    float ss = fmaf(xv.x,xv.x, fmaf(xv.y,xv.y, fmaf(xv.z,xv.z, xv.w*xv.w)));
    #pragma unroll
    for (int o = 16; o > 0; o >>= 1) {
        s  += __shfl_xor_sync(0xffffffffu, s,  o);
        ss += __shfl_xor_sync(0xffffffffu, ss, o);
    }
    __shared__ float sh_s[4], sh_ss[4];
    int w = tid >> 5;
    if ((tid & 31) == 0) { sh_s[w] = s; sh_ss[w] = ss; }
    __syncthreads();
    s  = sh_s[0] + sh_s[1] + sh_s[2] + sh_s[3];
    ss = sh_ss[0] + sh_ss[1] + sh_ss[2] + sh_ss[3];
    const float mu  = s * (1.f/512.f);
    const float var = ss * (1.f/512.f) - mu*mu;
    const float r   = rsqrtf(var + 1e-5f);
    float4 gv = *(const float4*)(g + tid*4);
    float4 bv = *(const float4*)(b + tid*4);
    float4 y;
    y.x = (xv.x - mu)*r*gv.x + bv.x;
    y.y = (xv.y - mu)*r*gv.y + bv.y;
    y.z = (xv.z - mu)*r*gv.z + bv.z;
    y.w = (xv.w - mu)*r*gv.w + bv.w;
    *(float4*)(Y + (size_t)row*DIMC + tid*4) = y;
}

// ---------------- launch ----------------
extern "C" void kernel_launch(void* const* d_in, const int* in_sizes, int n_in,
                              void* d_out, int out_size)
{
    (void)in_sizes; (void)n_in; (void)out_size;
    const float* x   = (const float*)d_in[0];
    const float* sk  = (const float*)d_in[1];
    const float* Wk  = (const float*)d_in[2];
    const float* bk  = (const float*)d_in[3];
    const float* Wq  = (const float*)d_in[4];
    const float* bq  = (const float*)d_in[5];
    const float* Wv  = (const float*)d_in[6];
    const float* bv  = (const float*)d_in[7];
    const float* sc  = (const float*)d_in[8];
    const float* lng = (const float*)d_in[9];
    const float* lnb = (const float*)d_in[10];
    const float* Wo  = (const float*)d_in[11];
    const float* bo  = (const float*)d_in[12];
    float* out = (float*)d_out;

    float *kp,*qp,*vp,*retp,*lnp,*wwp,*rwp;
    cudaGetSymbolAddress((void**)&kp,  g_k);
    cudaGetSymbolAddress((void**)&qp,  g_q);
    cudaGetSymbolAddress((void**)&vp,  g_v);
    cudaGetSymbolAddress((void**)&retp,g_ret);
    cudaGetSymbolAddress((void**)&lnp, g_ln);
    cudaGetSymbolAddress((void**)&wwp, g_ww);
    cudaGetSymbolAddress((void**)&rwp, g_rw);

    const int chunk_smem = (2*64*65 + 64*64) * (int)sizeof(float); // 49664 B
    cudaFuncSetAttribute(chunk_attn, cudaFuncAttributeMaxDynamicSharedMemorySize, chunk_smem);

    dim3 gg(DIMC/TBN, NTOK/TBM); // (4, 512)
    gemm_tf32<<<gg, 256>>>(x, Wk, bk, nullptr, kp, NTOK, DIMC, DIMC);
    gemm_tf32<<<gg, 256>>>(x, Wq, bq, nullptr, qp, NTOK, DIMC, DIMC);
    gemm_tf32<<<gg, 256>>>(x, Wv, bv, nullptr, vp, NTOK, DIMC, DIMC);

    slot_softmax<<<NTOK/64, 256>>>(kp, sk, sc, wwp);
    slot_softmax<<<NTOK/64, 256>>>(qp, sk, sc, rwp);

    chunk_attn<<<NCHUNK, 256, chunk_smem>>>(rwp, wwp, vp, retp);

    ln_kernel<<<NTOK, 128>>>(retp, lng, lnb, lnp);

    gemm_tf32<<<gg, 256>>>(lnp, Wo, bo, x, out, NTOK, DIMC, DIMC);
}

// round 3
// speedup vs baseline: 3.8679x; 1.8131x over previous
#include <cuda_runtime.h>
#include <math.h>

// Problem constants
#define NTOK (8*8192)        // 65536 tokens
#define DIMC 512
#define NSLOT 64
#define CHUNKT 64
#define NCHUNK (NTOK/CHUNKT) // 1024

// ---------------- scratch (device globals; no allocation allowed) ----------------
__device__ float g_v  [(size_t)NTOK*DIMC];
__device__ float g_ret[(size_t)NTOK*DIMC];
__device__ float g_ln [(size_t)NTOK*DIMC];
__device__ float g_ww [(size_t)NTOK*NSLOT];
__device__ float g_rw [(size_t)NTOK*NSLOT];
__device__ float g_Pk [DIMC*NSLOT];
__device__ float g_Pq [DIMC*NSLOT];
__device__ float g_ck [NSLOT];
__device__ float g_cq [NSLOT];

// ---------------- TF32 helpers ----------------
__device__ __forceinline__ unsigned f2tf32(float x) {
    unsigned r;
    asm("cvt.rna.tf32.f32 %0, %1;" : "=r"(r) : "f"(x));
    return r;
}

__device__ __forceinline__ void mma_tf32(float c[4],
    unsigned a0, unsigned a1, unsigned a2, unsigned a3,
    unsigned b0, unsigned b1)
{
    asm volatile(
        "mma.sync.aligned.m16n8k8.row.col.f32.tf32.tf32.f32 "
        "{%0,%1,%2,%3},{%4,%5,%6,%7},{%8,%9},{%0,%1,%2,%3};"
        : "+f"(c[0]), "+f"(c[1]), "+f"(c[2]), "+f"(c[3])
        : "r"(a0), "r"(a1), "r"(a2), "r"(a3), "r"(b0), "r"(b1));
}

// -------- prep: P = W @ SK^T (per input-dim row), c = b @ SK^T --------
__global__ __launch_bounds__(64) void prep_kernel(
    const float* __restrict__ Wk, const float* __restrict__ bk,
    const float* __restrict__ Wq, const float* __restrict__ bq,
    const float* __restrict__ SK,
    float* __restrict__ Pk, float* __restrict__ Pq,
    float* __restrict__ ck, float* __restrict__ cq)
{
    __shared__ float rk[DIMC];
    __shared__ float rq[DIMC];
    const int blk = blockIdx.x;
    const int s = threadIdx.x;
    if (blk < DIMC) {
        for (int d = s; d < DIMC; d += 64) {
            rk[d] = Wk[(size_t)blk*DIMC + d];
            rq[d] = Wq[(size_t)blk*DIMC + d];
        }
    } else {
        for (int d = s; d < DIMC; d += 64) { rk[d] = bk[d]; rq[d] = bq[d]; }
    }
    __syncthreads();
    float ak = 0.f, aq = 0.f;
    const float* skr = SK + (size_t)s*DIMC;
    #pragma unroll 8
    for (int d = 0; d < DIMC; d++) {
        float sv = skr[d];
        ak = fmaf(rk[d], sv, ak);
        aq = fmaf(rq[d], sv, aq);
    }
    if (blk < DIMC) { Pk[(size_t)blk*NSLOT + s] = ak; Pq[(size_t)blk*NSLOT + s] = aq; }
    else            { ck[s] = ak; cq[s] = aq; }
}

// ---------------- TF32 tensor-core GEMM (double-buffered via regs) ----------------
// C[M,N] = A[M,K] @ W[K,N] + bias (+resid). 128x128 tile, BK=32, 256 threads.
#define TBM 128
#define TBN 128
#define TBK 32
#define AS_STRIDE 36
#define BS_STRIDE 136

__global__ __launch_bounds__(256) void gemm_tf32(
    const float* __restrict__ A, const float* __restrict__ W,
    const float* __restrict__ bias, const float* __restrict__ resid,
    float* __restrict__ C, int M, int N, int K)
{
    __shared__ unsigned As[TBM][AS_STRIDE];
    __shared__ unsigned Bs[TBK][BS_STRIDE];

    const int tid  = threadIdx.x;
    const int lane = tid & 31;
    const int wid  = tid >> 5;
    const int warp_m = wid >> 2;   // 0..1
    const int warp_n = wid & 3;    // 0..3
    const int gid = lane >> 2;     // 0..7
    const int tig = lane & 3;      // 0..3
    const int m0 = blockIdx.y * TBM;
    const int n0 = blockIdx.x * TBN;

    const int a_row = tid >> 1;            // 0..127
    const int a_col = (tid & 1) * 16;      // 0/16
    const int b_row = tid >> 3;            // 0..31
    const int b_col = (tid & 7) * 16;      // 0..112

    float acc[4][4][4] = {};
    float4 pa[4], pb[4];

    const float* agb = A + (size_t)(m0 + a_row) * K + a_col;
    const float* bgb = W + (size_t)b_row * N + n0 + b_col;

    // prologue: fetch tile 0
    #pragma unroll
    for (int v = 0; v < 4; v++) pa[v] = *(const float4*)(agb + v * 4);
    #pragma unroll
    for (int v = 0; v < 4; v++) pb[v] = *(const float4*)(bgb + v * 4);

    for (int k0 = 0; k0 < K; k0 += TBK) {
        // store staged regs -> smem (tf32 round)
        #pragma unroll
        for (int v = 0; v < 4; v++) {
            uint4 u;
            u.x = f2tf32(pa[v].x); u.y = f2tf32(pa[v].y);
            u.z = f2tf32(pa[v].z); u.w = f2tf32(pa[v].w);
            *(uint4*)&As[a_row][a_col + v * 4] = u;
        }
        #pragma unroll
        for (int v = 0; v < 4; v++) {
            uint4 u;
            u.x = f2tf32(pb[v].x); u.y = f2tf32(pb[v].y);
            u.z = f2tf32(pb[v].z); u.w = f2tf32(pb[v].w);
            *(uint4*)&Bs[b_row][b_col + v * 4] = u;
        }
        __syncthreads();

        // prefetch next tile into regs (overlaps with MMA below)
        if (k0 + TBK < K) {
            const float* ag = agb + k0 + TBK;
            const float* bg = bgb + (size_t)(k0 + TBK) * N;
            #pragma unroll
            for (int v = 0; v < 4; v++) pa[v] = *(const float4*)(ag + v * 4);
            #pragma unroll
            for (int v = 0; v < 4; v++) pb[v] = *(const float4*)(bg + v * 4);
        }

        #pragma unroll
        for (int kk = 0; kk < TBK; kk += 8) {
            unsigned af[4][4];
            #pragma unroll
            for (int mt = 0; mt < 4; mt++) {
                int r = warp_m * 64 + mt * 16 + gid;
                af[mt][0] = As[r    ][kk + tig    ];
                af[mt][1] = As[r + 8][kk + tig    ];
                af[mt][2] = As[r    ][kk + tig + 4];
                af[mt][3] = As[r + 8][kk + tig + 4];
            }
            unsigned bf[4][2];
            #pragma unroll
            for (int nt = 0; nt < 4; nt++) {
                int c = warp_n * 32 + nt * 8 + gid;
                bf[nt][0] = Bs[kk + tig    ][c];
                bf[nt][1] = Bs[kk + tig + 4][c];
            }
            #pragma unroll
            for (int mt = 0; mt < 4; mt++)
                #pragma unroll
                for (int nt = 0; nt < 4; nt++)
                    mma_tf32(acc[mt][nt], af[mt][0], af[mt][1], af[mt][2], af[mt][3],
                             bf[nt][0], bf[nt][1]);
        }
        __syncthreads();
    }

    #pragma unroll
    for (int nt = 0; nt < 4; nt++) {
        int cb = n0 + warp_n * 32 + nt * 8 + 2 * tig;
        float b0 = bias[cb], b1 = bias[cb + 1];
        #pragma unroll
        for (int mt = 0; mt < 4; mt++) {
            int r0 = m0 + warp_m * 64 + mt * 16 + gid;
            int r1 = r0 + 8;
            size_t off0 = (size_t)r0 * N + cb;
            size_t off1 = (size_t)r1 * N + cb;
            float2 o0, o1;
            o0.x = acc[mt][nt][0] + b0; o0.y = acc[mt][nt][1] + b1;
            o1.x = acc[mt][nt][2] + b0; o1.y = acc[mt][nt][3] + b1;
            if (resid) {
                float2 e0 = *(const float2*)(resid + off0);
                float2 e1 = *(const float2*)(resid + off1);
                o0.x += e0.x; o0.y += e0.y;
                o1.x += e1.x; o1.y += e1.y;
            }
            *(float2*)(C + off0) = o0;
            *(float2*)(C + off1) = o1;
        }
    }
}

// -------- fused logits + softmax for BOTH ww and rw --------
// ww[tok,s] = softmax_s( (x @ Pk + ck)[s] * scale ); rw likewise with Pq,cq.
// Block: 128 tokens x 64 slots, K=512, TBK=32. 8 warps: 4(m) x 2(n), warp tile 32x32.
#define LAS 36
#define LBS 68
#define LSM_BYTES 35840   // max(As 18432 + 2*Bs 8704 each, L 33280)

__global__ __launch_bounds__(256) void logits_softmax(
    const float* __restrict__ X,
    const float* __restrict__ Pk, const float* __restrict__ Pq,
    const float* __restrict__ ck, const float* __restrict__ cq,
    const float* __restrict__ scale_p,
    float* __restrict__ ww, float* __restrict__ rw)
{
    __shared__ __align__(16) char sbuf[LSM_BYTES];
    unsigned (*As)[LAS]  = (unsigned (*)[LAS])sbuf;
    unsigned (*Bk)[LBS]  = (unsigned (*)[LBS])(sbuf + 18432);
    unsigned (*Bq)[LBS]  = (unsigned (*)[LBS])(sbuf + 18432 + 8704);
    float* L = (float*)sbuf;                // aliases staging (used after final sync)
    __shared__ float csh_k[64], csh_q[64];

    const int tid  = threadIdx.x;
    const int lane = tid & 31;
    const int wid  = tid >> 5;
    const int warp_m = wid >> 1;   // 0..3 -> 32-row slab
    const int warp_n = wid & 1;    // 0..1 -> 32-col slab
    const int gid = lane >> 2;
    const int tig = lane & 3;
    const int tok0 = blockIdx.x * 128;

    if (tid < 64) { csh_k[tid] = ck[tid]; csh_q[tid] = cq[tid]; }

    const int a_row = tid >> 1;
    const int a_col = (tid & 1) * 16;
    const int b_row = tid >> 3;            // 0..31
    const int b_col = (tid & 7) * 8;       // 0..56

    float acck[2][4][4] = {};
    float accq[2][4][4] = {};
    float4 pa[4], pbk[2], pbq[2];

    const float* agb  = X  + (size_t)(tok0 + a_row) * DIMC + a_col;
    const float* bkb  = Pk + (size_t)b_row * NSLOT + b_col;
    const float* bqb  = Pq + (size_t)b_row * NSLOT + b_col;

    #pragma unroll
    for (int v = 0; v < 4; v++) pa[v] = *(const float4*)(agb + v * 4);
    pbk[0] = *(const float4*)(bkb); pbk[1] = *(const float4*)(bkb + 4);
    pbq[0] = *(const float4*)(bqb); pbq[1] = *(const float4*)(bqb + 4);

    for (int k0 = 0; k0 < DIMC; k0 += TBK) {
        #pragma unroll
        for (int v = 0; v < 4; v++) {
            uint4 u;
            u.x = f2tf32(pa[v].x); u.y = f2tf32(pa[v].y);
            u.z = f2tf32(pa[v].z); u.w = f2tf32(pa[v].w);
            *(uint4*)&As[a_row][a_col + v * 4] = u;
        }
        {
            uint4 u0, u1;
            u0.x = f2tf32(pbk[0].x); u0.y = f2tf32(pbk[0].y);
            u0.z = f2tf32(pbk[0].z); u0.w = f2tf32(pbk[0].w);
            u1.x = f2tf32(pbk[1].x); u1.y = f2tf32(pbk[1].y);
            u1.z = f2tf32(pbk[1].z); u1.w = f2tf32(pbk[1].w);
            *(uint4*)&Bk[b_row][b_col]     = u0;
            *(uint4*)&Bk[b_row][b_col + 4] = u1;
            u0.x = f2tf32(pbq[0].x); u0.y = f2tf32(pbq[0].y);
            u0.z = f2tf32(pbq[0].z); u0.w = f2tf32(pbq[0].w);
            u1.x = f2tf32(pbq[1].x); u1.y = f2tf32(pbq[1].y);
            u1.z = f2tf32(pbq[1].z); u1.w = f2tf32(pbq[1].w);
            *(uint4*)&Bq[b_row][b_col]     = u0;
            *(uint4*)&Bq[b_row][b_col + 4] = u1;
        }
        __syncthreads();

        if (k0 + TBK < DIMC) {
            const float* ag = agb + k0 + TBK;
            const float* bk2 = bkb + (size_t)(k0 + TBK) * NSLOT;
            const float* bq2 = bqb + (size_t)(k0 + TBK) * NSLOT;
            #pragma unroll
            for (int v = 0; v < 4; v++) pa[v] = *(const float4*)(ag + v * 4);
            pbk[0] = *(const float4*)(bk2); pbk[1] = *(const float4*)(bk2 + 4);
            pbq[0] = *(const float4*)(bq2); pbq[1] = *(const float4*)(bq2 + 4);
        }

        #pragma unroll
        for (int kk = 0; kk < TBK; kk += 8) {
            unsigned af[2][4];
            #pragma unroll
            for (int mt = 0; mt < 2; mt++) {
                int r = warp_m * 32 + mt * 16 + gid;
                af[mt][0] = As[r    ][kk + tig    ];
                af[mt][1] = As[r + 8][kk + tig    ];
                af[mt][2] = As[r    ][kk + tig + 4];
                af[mt][3] = As[r + 8][kk + tig + 4];
            }
            unsigned bfk[4][2], bfq[4][2];
            #pragma unroll
            for (int nt = 0; nt < 4; nt++) {
                int c = warp_n * 32 + nt * 8 + gid;
                bfk[nt][0] = Bk[kk + tig    ][c];
                bfk[nt][1] = Bk[kk + tig + 4][c];
                bfq[nt][0] = Bq[kk + tig    ][c];
                bfq[nt][1] = Bq[kk + tig + 4][c];
            }
            #pragma unroll
            for (int mt = 0; mt < 2; mt++)
                #pragma unroll
                for (int nt = 0; nt < 4; nt++) {
                    mma_tf32(acck[mt][nt], af[mt][0], af[mt][1], af[mt][2], af[mt][3],
                             bfk[nt][0], bfk[nt][1]);
                    mma_tf32(accq[mt][nt], af[mt][0], af[mt][1], af[mt][2], af[mt][3],
                             bfq[nt][0], bfq[nt][1]);
                }
        }
        __syncthreads();
    }

    const float sc = scale_p[0];

    // two epilogue passes over the same L buffer
    #pragma unroll
    for (int pass = 0; pass < 2; pass++) {
        float (*acc)[4][4] = pass ? accq : acck;
        const float* csh = pass ? csh_q : csh_k;
        float* outp = pass ? rw : ww;

        #pragma unroll
        for (int mt = 0; mt < 2; mt++) {
            int r0 = warp_m * 32 + mt * 16 + gid;
            #pragma unroll
            for (int nt = 0; nt < 4; nt++) {
                int c0 = warp_n * 32 + nt * 8 + 2 * tig;
                L[r0*65 + c0]       = (acc[mt][nt][0] + csh[c0])   * sc;
                L[r0*65 + c0+1]     = (acc[mt][nt][1] + csh[c0+1]) * sc;
                L[(r0+8)*65 + c0]   = (acc[mt][nt][2] + csh[c0])   * sc;
                L[(r0+8)*65 + c0+1] = (acc[mt][nt][3] + csh[c0+1]) * sc;
            }
        }
        __syncthreads();

        // softmax: 2 threads per row (32 slots each)
        {
            int t = tid >> 1, h = tid & 1;
            float* Lr = L + t*65 + h*32;
            float mx = -1e30f;
            #pragma unroll 8
            for (int s = 0; s < 32; s++) mx = fmaxf(mx, Lr[s]);
            mx = fmaxf(mx, __shfl_xor_sync(0xffffffffu, mx, 1));
            float sum = 0.f;
            #pragma unroll 8
            for (int s = 0; s < 32; s++) { float e = expf(Lr[s]-mx); Lr[s] = e; sum += e; }
            sum += __shfl_xor_sync(0xffffffffu, sum, 1);
            float rv = 1.f / sum;
            float* op = outp + (size_t)(tok0 + t) * NSLOT + h*32;
            #pragma unroll
            for (int s = 0; s < 32; s += 4) {
                float4 w;
                w.x = Lr[s]*rv; w.y = Lr[s+1]*rv; w.z = Lr[s+2]*rv; w.w = Lr[s+3]*rv;
                *(float4*)(op + s) = w;
            }
        }
        __syncthreads();
    }
}

// -------- per-chunk: A = rw @ ww^T (causal-masked), retrieved = A @ v --------
__global__ __launch_bounds__(256) void chunk_attn(
    const float* __restrict__ rw, const float* __restrict__ ww,
    const float* __restrict__ v, float* __restrict__ ret)
{
    extern __shared__ float cbuf[];
    float* RW = cbuf;              // [64][65]
    float* WW = cbuf + 64*65;      // [64][65]
    float* Vs = cbuf + 2*64*65;    // [64][64]
    const int tid = threadIdx.x;
    const int tx = tid & 15, ty = tid >> 4;
    const int c0 = blockIdx.x * CHUNKT;

    for (int i = tid; i < 64*64; i += 256) {
        int r = i >> 6, s = i & 63;
        RW[r*65+s] = rw[(size_t)(c0+r)*NSLOT + s];
        WW[r*65+s] = ww[(size_t)(c0+r)*NSLOT + s];
    }
    __syncthreads();

    float a4[4][4] = {};
    for (int s = 0; s < 64; s++) {
        float ra[4], wb[4];
        #pragma unroll
        for (int i = 0; i < 4; i++) ra[i] = RW[(ty*4+i)*65 + s];
        #pragma unroll
        for (int j = 0; j < 4; j++) wb[j] = WW[(tx*4+j)*65 + s];
        #pragma unroll
        for (int i = 0; i < 4; i++)
            #pragma unroll
            for (int j = 0; j < 4; j++)
                a4[i][j] = fmaf(ra[i], wb[j], a4[i][j]);
    }
    __syncthreads();

    #pragma unroll
    for (int i = 0; i < 4; i++) {
        int t = ty*4 + i;
        #pragma unroll
        for (int j = 0; j < 4; j++) {
            int u = tx*4 + j;
            RW[t*65+u] = (u <= t) ? a4[i][j] : 0.f;
        }
    }
    __syncthreads();
    float* Amat = RW;

    for (int d0 = 0; d0 < DIMC; d0 += 64) {
        for (int i = tid; i < 1024; i += 256) {
            int r = i >> 4, c = (i & 15) << 2;
            *(float4*)&Vs[r*64+c] = *(const float4*)(v + (size_t)(c0+r)*DIMC + d0 + c);
        }
        __syncthreads();
        float racc[4][4] = {};
        for (int u = 0; u < 64; u++) {
            float av[4];
            #pragma unroll
            for (int i = 0; i < 4; i++) av[i] = Amat[(ty*4+i)*65 + u];
            float4 vv = *(float4*)&Vs[u*64 + tx*4];
            #pragma unroll
            for (int i = 0; i < 4; i++) {
                racc[i][0] = fmaf(av[i], vv.x, racc[i][0]);
                racc[i][1] = fmaf(av[i], vv.y, racc[i][1]);
                racc[i][2] = fmaf(av[i], vv.z, racc[i][2]);
                racc[i][3] = fmaf(av[i], vv.w, racc[i][3]);
            }
        }
        #pragma unroll
        for (int i = 0; i < 4; i++) {
            float4 o; o.x = racc[i][0]; o.y = racc[i][1]; o.z = racc[i][2]; o.w = racc[i][3];
            *(float4*)(ret + (size_t)(c0+ty*4+i)*DIMC + d0 + tx*4) = o;
        }
        __syncthreads();
    }
}

// -------- LayerNorm over last dim (512) --------
__global__ __launch_bounds__(128) void ln_kernel(
    const float* __restrict__ X, const float* __restrict__ g,
    const float* __restrict__ b, float* __restrict__ Y)
{
    const int row = blockIdx.x;
    const int tid = threadIdx.x;
    float4 xv = *(const float4*)(X + (size_t)row*DIMC + tid*4);
    float s  = xv.x + xv.y + xv.z + xv.w;
    float ss = fmaf(xv.x,xv.x, fmaf(xv.y,xv.y, fmaf(xv.z,xv.z, xv.w*xv.w)));
    #pragma unroll
    for (int o = 16; o > 0; o >>= 1) {
        s  += __shfl_xor_sync(0xffffffffu, s,  o);
        ss += __shfl_xor_sync(0xffffffffu, ss, o);
    }
    __shared__ float sh_s[4], sh_ss[4];
    int w = tid >> 5;
    if ((tid & 31) == 0) { sh_s[w] = s; sh_ss[w] = ss; }
    __syncthreads();
    s  = sh_s[0] + sh_s[1] + sh_s[2] + sh_s[3];
    ss = sh_ss[0] + sh_ss[1] + sh_ss[2] + sh_ss[3];
    const float mu  = s * (1.f/512.f);
    const float var = ss * (1.f/512.f) - mu*mu;
    const float r   = rsqrtf(var + 1e-5f);
    float4 gv = *(const float4*)(g + tid*4);
    float4 bv = *(const float4*)(b + tid*4);
    float4 y;
    y.x = (xv.x - mu)*r*gv.x + bv.x;
    y.y = (xv.y - mu)*r*gv.y + bv.y;
    y.z = (xv.z - mu)*r*gv.z + bv.z;
    y.w = (xv.w - mu)*r*gv.w + bv.w;
    *(float4*)(Y + (size_t)row*DIMC + tid*4) = y;
}

// ---------------- launch ----------------
extern "C" void kernel_launch(void* const* d_in, const int* in_sizes, int n_in,
                              void* d_out, int out_size)
{
    (void)in_sizes; (void)n_in; (void)out_size;
    const float* x   = (const float*)d_in[0];
    const float* sk  = (const float*)d_in[1];
    const float* Wk  = (const float*)d_in[2];
    const float* bk  = (const float*)d_in[3];
    const float* Wq  = (const float*)d_in[4];
    const float* bq  = (const float*)d_in[5];
    const float* Wv  = (const float*)d_in[6];
    const float* bv  = (const float*)d_in[7];
    const float* sc  = (const float*)d_in[8];
    const float* lng = (const float*)d_in[9];
    const float* lnb = (const float*)d_in[10];
    const float* Wo  = (const float*)d_in[11];
    const float* bo  = (const float*)d_in[12];
    float* out = (float*)d_out;

    float *vp,*retp,*lnp,*wwp,*rwp,*Pkp,*Pqp,*ckp,*cqp;
    cudaGetSymbolAddress((void**)&vp,  g_v);
    cudaGetSymbolAddress((void**)&retp,g_ret);
    cudaGetSymbolAddress((void**)&lnp, g_ln);
    cudaGetSymbolAddress((void**)&wwp, g_ww);
    cudaGetSymbolAddress((void**)&rwp, g_rw);
    cudaGetSymbolAddress((void**)&Pkp, g_Pk);
    cudaGetSymbolAddress((void**)&Pqp, g_Pq);
    cudaGetSymbolAddress((void**)&ckp, g_ck);
    cudaGetSymbolAddress((void**)&cqp, g_cq);

    const int chunk_smem = (2*64*65 + 64*64) * (int)sizeof(float); // 49664 B
    cudaFuncSetAttribute(chunk_attn, cudaFuncAttributeMaxDynamicSharedMemorySize, chunk_smem);

    prep_kernel<<<DIMC + 1, 64>>>(Wk, bk, Wq, bq, sk, Pkp, Pqp, ckp, cqp);

    dim3 gg(DIMC/TBN, NTOK/TBM); // (4, 512)
    gemm_tf32<<<gg, 256>>>(x, Wv, bv, nullptr, vp, NTOK, DIMC, DIMC);

    logits_softmax<<<NTOK/128, 256>>>(x, Pkp, Pqp, ckp, cqp, sc, wwp, rwp);

    chunk_attn<<<NCHUNK, 256, chunk_smem>>>(rwp, wwp, vp, retp);

    ln_kernel<<<NTOK, 128>>>(retp, lng, lnb, lnp);

    gemm_tf32<<<gg, 256>>>(lnp, Wo, bo, x, out, NTOK, DIMC, DIMC);
}

// round 4
// speedup vs baseline: 4.0532x; 1.0479x over previous
#include <cuda_runtime.h>
#include <math.h>

// Problem constants
#define NTOK (8*8192)        // 65536 tokens
#define DIMC 512
#define NSLOT 64
#define CHUNKT 64
#define NCHUNK (NTOK/CHUNKT) // 1024

// ---------------- scratch (device globals; no allocation allowed) ----------------
__device__ float g_v  [(size_t)NTOK*DIMC];
__device__ float g_ret[(size_t)NTOK*DIMC];
__device__ float g_ln [(size_t)NTOK*DIMC];
__device__ float g_ww [(size_t)NTOK*NSLOT];
__device__ float g_rw [(size_t)NTOK*NSLOT];
__device__ float g_P  [DIMC*128];   // [Pk | Pq] concat: row d, col s (0..63 k, 64..127 q)
__device__ float g_c  [128];        // [ck | cq]

// ---------------- TF32 / cp.async helpers ----------------
__device__ __forceinline__ unsigned f2tf32(float x) {
    unsigned r;
    asm("cvt.rna.tf32.f32 %0, %1;" : "=r"(r) : "f"(x));
    return r;
}

__device__ __forceinline__ void mma_tf32(float c[4],
    unsigned a0, unsigned a1, unsigned a2, unsigned a3,
    unsigned b0, unsigned b1)
{
    asm volatile(
        "mma.sync.aligned.m16n8k8.row.col.f32.tf32.tf32.f32 "
        "{%0,%1,%2,%3},{%4,%5,%6,%7},{%8,%9},{%0,%1,%2,%3};"
        : "+f"(c[0]), "+f"(c[1]), "+f"(c[2]), "+f"(c[3])
        : "r"(a0), "r"(a1), "r"(a2), "r"(a3), "r"(b0), "r"(b1));
}

__device__ __forceinline__ void cp16(unsigned smem_addr, const void* g) {
    asm volatile("cp.async.ca.shared.global [%0], [%1], 16;\n"
                 :: "r"(smem_addr), "l"(g));
}
#define CP_COMMIT() asm volatile("cp.async.commit_group;\n" ::: "memory")
#define CP_WAIT0()  asm volatile("cp.async.wait_group 0;\n" ::: "memory")

// -------- prep: P[:,s<64] = Wk @ SKᵀ, P[:,s>=64] = Wq @ SKᵀ; c likewise from biases --------
__global__ __launch_bounds__(128) void prep_kernel(
    const float* __restrict__ Wk, const float* __restrict__ bk,
    const float* __restrict__ Wq, const float* __restrict__ bq,
    const float* __restrict__ SK,
    float* __restrict__ P, float* __restrict__ c)
{
    __shared__ float rk[DIMC];
    __shared__ float rq[DIMC];
    const int blk = blockIdx.x;
    const int s = threadIdx.x;          // 0..127
    const int slot = s & 63;
    if (blk < DIMC) {
        for (int d = s; d < DIMC; d += 128) {
            rk[d] = Wk[(size_t)blk*DIMC + d];
            rq[d] = Wq[(size_t)blk*DIMC + d];
        }
    } else {
        for (int d = s; d < DIMC; d += 128) { rk[d] = bk[d]; rq[d] = bq[d]; }
    }
    __syncthreads();
    const float* row = (s < 64) ? rk : rq;
    float a = 0.f;
    const float* skr = SK + (size_t)slot*DIMC;
    #pragma unroll 8
    for (int d = 0; d < DIMC; d++) a = fmaf(row[d], skr[d], a);
    if (blk < DIMC) P[(size_t)blk*128 + s] = a;
    else            c[s] = a;
}

// ---------------- fused TF32 GEMM (cp.async 2-stage) ----------------
// grid (nx, M/128). blocks x < nNormal: C[:,x*128..] = A@W + bias (+resid)
// block x == nNormal (if P != null): logits = (A@P + c)*scale, row-softmax over
//   each 64-wide half -> ww (cols 0..63) and rw (cols 64..127).
#define TBM 128
#define TBN 128
#define TBK 32
#define ASRD 36
#define BSRD 136
#define GSMEM 71680   // 2*128*36*4 + 2*32*136*4

__global__ __launch_bounds__(256) void gemm_fused(
    const float* __restrict__ A, const float* __restrict__ W,
    const float* __restrict__ bias, const float* __restrict__ resid,
    float* __restrict__ C,
    const float* __restrict__ P, const float* __restrict__ cvec,
    const float* __restrict__ scale_p,
    float* __restrict__ ww, float* __restrict__ rw,
    int M, int K, int nNormal)
{
    extern __shared__ __align__(16) char smraw[];
    float (*As)[TBM][ASRD] = (float (*)[TBM][ASRD])smraw;                 // 2 stages
    float (*Bs)[TBK][BSRD] = (float (*)[TBK][BSRD])(smraw + 2*TBM*ASRD*4);
    float* L = (float*)smraw;   // logits epilogue alias: [128][132]
    __shared__ float csh[128];

    const int tid  = threadIdx.x;
    const int lane = tid & 31;
    const int wid  = tid >> 5;
    const int warp_m = wid >> 2;   // 0..1
    const int warp_n = wid & 3;    // 0..3
    const int gid = lane >> 2;
    const int tig = lane & 3;
    const int m0 = blockIdx.y * TBM;
    const bool is_logit = (P != nullptr) && ((int)blockIdx.x == nNormal);
    const int n0 = is_logit ? 0 : blockIdx.x * TBN;
    const float* Bsrc = is_logit ? P : W;
    const int ldB = is_logit ? 128 : DIMC;

    const int a_row = tid >> 1;
    const int a_colb = (tid & 1) * 16;
    const int b_row = tid >> 3;
    const int b_colb = (tid & 7) * 16;

    if (is_logit && tid < 128) csh[tid] = cvec[tid];

    const unsigned as_base = (unsigned)__cvta_generic_to_shared(smraw);
    const unsigned bs_base = as_base + 2*TBM*ASRD*4;

    const float* agb = A + (size_t)(m0 + a_row) * K + a_colb;
    const float* bgb = Bsrc + (size_t)b_row * ldB + n0 + b_colb;

    float acc[4][4][4] = {};

    // prologue: stage 0
    {
        unsigned as = as_base + (unsigned)(((0*TBM + a_row)*ASRD + a_colb)*4);
        #pragma unroll
        for (int v = 0; v < 4; v++) cp16(as + v*16, agb + v*4);
        unsigned bs = bs_base + (unsigned)(((0*TBK + b_row)*BSRD + b_colb)*4);
        #pragma unroll
        for (int v = 0; v < 4; v++) cp16(bs + v*16, bgb + v*4);
        CP_COMMIT();
    }

    const int nIter = K / TBK;
    for (int it = 0; it < nIter; it++) {
        CP_WAIT0();
        __syncthreads();
        if (it + 1 < nIter) {
            int st = (it + 1) & 1;
            int k0 = (it + 1) * TBK;
            unsigned as = as_base + (unsigned)(((st*TBM + a_row)*ASRD + a_colb)*4);
            const float* ag = agb + k0;
            #pragma unroll
            for (int v = 0; v < 4; v++) cp16(as + v*16, ag + v*4);
            unsigned bs = bs_base + (unsigned)(((st*TBK + b_row)*BSRD + b_colb)*4);
            const float* bg = bgb + (size_t)k0 * ldB;
            #pragma unroll
            for (int v = 0; v < 4; v++) cp16(bs + v*16, bg + v*4);
            CP_COMMIT();
        }
        const int st = it & 1;
        #pragma unroll
        for (int kk = 0; kk < TBK; kk += 8) {
            unsigned af[4][4];
            #pragma unroll
            for (int mt = 0; mt < 4; mt++) {
                int r = warp_m * 64 + mt * 16 + gid;
                af[mt][0] = f2tf32(As[st][r    ][kk + tig    ]);
                af[mt][1] = f2tf32(As[st][r + 8][kk + tig    ]);
                af[mt][2] = f2tf32(As[st][r    ][kk + tig + 4]);
                af[mt][3] = f2tf32(As[st][r + 8][kk + tig + 4]);
            }
            unsigned bf[4][2];
            #pragma unroll
            for (int nt = 0; nt < 4; nt++) {
                int cc = warp_n * 32 + nt * 8 + gid;
                bf[nt][0] = f2tf32(Bs[st][kk + tig    ][cc]);
                bf[nt][1] = f2tf32(Bs[st][kk + tig + 4][cc]);
            }
            #pragma unroll
            for (int mt = 0; mt < 4; mt++)
                #pragma unroll
                for (int nt = 0; nt < 4; nt++)
                    mma_tf32(acc[mt][nt], af[mt][0], af[mt][1], af[mt][2], af[mt][3],
                             bf[nt][0], bf[nt][1]);
        }
        __syncthreads();
    }

    if (!is_logit) {
        #pragma unroll
        for (int nt = 0; nt < 4; nt++) {
            int cb = n0 + warp_n * 32 + nt * 8 + 2 * tig;
            float b0 = bias[cb], b1 = bias[cb + 1];
            #pragma unroll
            for (int mt = 0; mt < 4; mt++) {
                int r0 = m0 + warp_m * 64 + mt * 16 + gid;
                int r1 = r0 + 8;
                size_t off0 = (size_t)r0 * DIMC + cb;
                size_t off1 = (size_t)r1 * DIMC + cb;
                float2 o0, o1;
                o0.x = acc[mt][nt][0] + b0; o0.y = acc[mt][nt][1] + b1;
                o1.x = acc[mt][nt][2] + b0; o1.y = acc[mt][nt][3] + b1;
                if (resid) {
                    float2 e0 = *(const float2*)(resid + off0);
                    float2 e1 = *(const float2*)(resid + off1);
                    o0.x += e0.x; o0.y += e0.y;
                    o1.x += e1.x; o1.y += e1.y;
                }
                *(float2*)(C + off0) = o0;
                *(float2*)(C + off1) = o1;
            }
        }
    } else {
        // logits epilogue: L[r][c] = (acc + c[c]) * scale, then row-softmax per 64-half
        const float sc = scale_p[0];
        #pragma unroll
        for (int nt = 0; nt < 4; nt++) {
            int cb = warp_n * 32 + nt * 8 + 2 * tig;
            float c0v = csh[cb], c1v = csh[cb + 1];
            #pragma unroll
            for (int mt = 0; mt < 4; mt++) {
                int r0 = warp_m * 64 + mt * 16 + gid;
                L[r0*132 + cb]       = (acc[mt][nt][0] + c0v) * sc;
                L[r0*132 + cb+1]     = (acc[mt][nt][1] + c1v) * sc;
                L[(r0+8)*132 + cb]   = (acc[mt][nt][2] + c0v) * sc;
                L[(r0+8)*132 + cb+1] = (acc[mt][nt][3] + c1v) * sc;
            }
        }
        __syncthreads();
        {
            int row = tid >> 1, h = tid & 1;
            float* Lr = L + row*132 + h*64;
            float mx = -1e30f;
            #pragma unroll 8
            for (int s = 0; s < 64; s++) mx = fmaxf(mx, Lr[s]);
            float sum = 0.f;
            #pragma unroll 8
            for (int s = 0; s < 64; s++) { float e = expf(Lr[s]-mx); Lr[s] = e; sum += e; }
            float rv = 1.f / sum;
            float* op = (h ? rw : ww) + (size_t)(m0 + row) * NSLOT;
            #pragma unroll
            for (int s = 0; s < 64; s += 4) {
                float4 w;
                w.x = Lr[s]*rv; w.y = Lr[s+1]*rv; w.z = Lr[s+2]*rv; w.w = Lr[s+3]*rv;
                *(float4*)(op + s) = w;
            }
        }
    }
}

// -------- per-chunk MMA: A = rw @ wwᵀ (causal), retrieved = A @ v --------
// 256 threads. smem: RW[64][68] (tf32; becomes Amat), WT[64][68] (wwᵀ tf32), VS[64][132] tf32.
#define CSMEM (64*68*4*2 + 64*132*4)   // 68608

__global__ __launch_bounds__(256) void chunk_attn_mma(
    const float* __restrict__ rw, const float* __restrict__ ww,
    const float* __restrict__ v, float* __restrict__ ret)
{
    extern __shared__ __align__(16) char cb[];
    unsigned* RW = (unsigned*)cb;            // [64][68], later Amat
    unsigned* WT = RW + 64*68;               // [64][68]  (WT[s][u] = ww[u][s])
    unsigned* VS = WT + 64*68;               // [64][132]
    const int tid  = threadIdx.x;
    const int lane = tid & 31;
    const int wid  = tid >> 5;
    const int gid = lane >> 2;
    const int tig = lane & 3;
    const int chunk0 = blockIdx.x * CHUNKT;

    // load rw (tf32) and ww transposed (tf32)
    #pragma unroll
    for (int k = 0; k < 4; k++) {
        int idx = tid + k*256;               // 1024 float4 chunks: 64 rows x 16
        int r = idx >> 4, c4 = (idx & 15) << 2;
        float4 a = *(const float4*)(rw + (size_t)(chunk0+r)*NSLOT + c4);
        RW[r*68 + c4    ] = f2tf32(a.x);
        RW[r*68 + c4 + 1] = f2tf32(a.y);
        RW[r*68 + c4 + 2] = f2tf32(a.z);
        RW[r*68 + c4 + 3] = f2tf32(a.w);
        float4 b = *(const float4*)(ww + (size_t)(chunk0+r)*NSLOT + c4);
        WT[(c4    )*68 + r] = f2tf32(b.x);
        WT[(c4 + 1)*68 + r] = f2tf32(b.y);
        WT[(c4 + 2)*68 + r] = f2tf32(b.z);
        WT[(c4 + 3)*68 + r] = f2tf32(b.w);
    }
    __syncthreads();

    // ---- mma1: A(64x64) = RW(64x64) @ WTᵀ ; warps 2(m) x 4(n), warp tile 32x16 ----
    const int wm = wid >> 2;   // 0..1
    const int wn = wid & 3;    // 0..3
    float a1[2][2][4] = {};
    #pragma unroll
    for (int kk = 0; kk < 64; kk += 8) {
        unsigned af[2][4];
        #pragma unroll
        for (int mt = 0; mt < 2; mt++) {
            int r = wm*32 + mt*16 + gid;
            af[mt][0] = RW[ r     *68 + kk + tig    ];
            af[mt][1] = RW[(r + 8)*68 + kk + tig    ];
            af[mt][2] = RW[ r     *68 + kk + tig + 4];
            af[mt][3] = RW[(r + 8)*68 + kk + tig + 4];
        }
        unsigned bf[2][2];
        #pragma unroll
        for (int nt = 0; nt < 2; nt++) {
            int cc = wn*16 + nt*8 + gid;
            bf[nt][0] = WT[(kk + tig    )*68 + cc];
            bf[nt][1] = WT[(kk + tig + 4)*68 + cc];
        }
        #pragma unroll
        for (int mt = 0; mt < 2; mt++)
            #pragma unroll
            for (int nt = 0; nt < 2; nt++)
                mma_tf32(a1[mt][nt], af[mt][0], af[mt][1], af[mt][2], af[mt][3],
                         bf[nt][0], bf[nt][1]);
    }
    __syncthreads();   // done reading RW; now overwrite with masked Amat (tf32)

    #pragma unroll
    for (int mt = 0; mt < 2; mt++) {
        int r0 = wm*32 + mt*16 + gid;
        #pragma unroll
        for (int nt = 0; nt < 2; nt++) {
            int cc = wn*16 + nt*8 + 2*tig;
            RW[ r0    *68 + cc    ] = f2tf32((cc     <= r0    ) ? a1[mt][nt][0] : 0.f);
            RW[ r0    *68 + cc + 1] = f2tf32((cc + 1 <= r0    ) ? a1[mt][nt][1] : 0.f);
            RW[(r0+8) *68 + cc    ] = f2tf32((cc     <= r0 + 8) ? a1[mt][nt][2] : 0.f);
            RW[(r0+8) *68 + cc + 1] = f2tf32((cc + 1 <= r0 + 8) ? a1[mt][nt][3] : 0.f);
        }
    }
    __syncthreads();

    // cache all A fragments in regs (reused across 4 d-slices)
    unsigned afA[8][2][4];
    #pragma unroll
    for (int ks = 0; ks < 8; ks++) {
        #pragma unroll
        for (int mt = 0; mt < 2; mt++) {
            int r = wm*32 + mt*16 + gid;
            afA[ks][mt][0] = RW[ r     *68 + ks*8 + tig    ];
            afA[ks][mt][1] = RW[(r + 8)*68 + ks*8 + tig    ];
            afA[ks][mt][2] = RW[ r     *68 + ks*8 + tig + 4];
            afA[ks][mt][3] = RW[(r + 8)*68 + ks*8 + tig + 4];
        }
    }

    // ---- mma2: ret(64x512) = A(64x64) @ V(64x512), 4 slices of 128 ----
    for (int d0 = 0; d0 < DIMC; d0 += 128) {
        #pragma unroll
        for (int k = 0; k < 8; k++) {
            int idx = tid + k*256;           // 2048 float4: 64 rows x 32
            int r = idx >> 5, c4 = (idx & 31) << 2;
            float4 a = *(const float4*)(v + (size_t)(chunk0+r)*DIMC + d0 + c4);
            VS[r*132 + c4    ] = f2tf32(a.x);
            VS[r*132 + c4 + 1] = f2tf32(a.y);
            VS[r*132 + c4 + 2] = f2tf32(a.z);
            VS[r*132 + c4 + 3] = f2tf32(a.w);
        }
        __syncthreads();

        float a2[2][4][4] = {};
        #pragma unroll
        for (int ks = 0; ks < 8; ks++) {
            unsigned bf[4][2];
            #pragma unroll
            for (int nt = 0; nt < 4; nt++) {
                int cc = wn*32 + nt*8 + gid;
                bf[nt][0] = VS[(ks*8 + tig    )*132 + cc];
                bf[nt][1] = VS[(ks*8 + tig + 4)*132 + cc];
            }
            #pragma unroll
            for (int mt = 0; mt < 2; mt++)
                #pragma unroll
                for (int nt = 0; nt < 4; nt++)
                    mma_tf32(a2[mt][nt], afA[ks][mt][0], afA[ks][mt][1],
                             afA[ks][mt][2], afA[ks][mt][3], bf[nt][0], bf[nt][1]);
        }

        #pragma unroll
        for (int mt = 0; mt < 2; mt++) {
            int r0 = wm*32 + mt*16 + gid;
            #pragma unroll
            for (int nt = 0; nt < 4; nt++) {
                int cc = wn*32 + nt*8 + 2*tig;
                float2 o0, o1;
                o0.x = a2[mt][nt][0]; o0.y = a2[mt][nt][1];
                o1.x = a2[mt][nt][2]; o1.y = a2[mt][nt][3];
                *(float2*)(ret + (size_t)(chunk0 + r0    )*DIMC + d0 + cc) = o0;
                *(float2*)(ret + (size_t)(chunk0 + r0 + 8)*DIMC + d0 + cc) = o1;
            }
        }
        __syncthreads();   // before next slice overwrites VS
    }
}

// -------- LayerNorm over last dim (512) --------
__global__ __launch_bounds__(128) void ln_kernel(
    const float* __restrict__ X, const float* __restrict__ g,
    const float* __restrict__ b, float* __restrict__ Y)
{
    const int row = blockIdx.x;
    const int tid = threadIdx.x;
    float4 xv = *(const float4*)(X + (size_t)row*DIMC + tid*4);
    float s  = xv.x + xv.y + xv.z + xv.w;
    float ss = fmaf(xv.x,xv.x, fmaf(xv.y,xv.y, fmaf(xv.z,xv.z, xv.w*xv.w)));
    #pragma unroll
    for (int o = 16; o > 0; o >>= 1) {
        s  += __shfl_xor_sync(0xffffffffu, s,  o);
        ss += __shfl_xor_sync(0xffffffffu, ss, o);
    }
    __shared__ float sh_s[4], sh_ss[4];
    int w = tid >> 5;
    if ((tid & 31) == 0) { sh_s[w] = s; sh_ss[w] = ss; }
    __syncthreads();
    s  = sh_s[0] + sh_s[1] + sh_s[2] + sh_s[3];
    ss = sh_ss[0] + sh_ss[1] + sh_ss[2] + sh_ss[3];
    const float mu  = s * (1.f/512.f);
    const float var = ss * (1.f/512.f) - mu*mu;
    const float r   = rsqrtf(var + 1e-5f);
    float4 gv = *(const float4*)(g + tid*4);
    float4 bv = *(const float4*)(b + tid*4);
    float4 y;
    y.x = (xv.x - mu)*r*gv.x + bv.x;
    y.y = (xv.y - mu)*r*gv.y + bv.y;
    y.z = (xv.z - mu)*r*gv.z + bv.z;
    y.w = (xv.w - mu)*r*gv.w + bv.w;
    *(float4*)(Y + (size_t)row*DIMC + tid*4) = y;
}

// ---------------- launch ----------------
extern "C" void kernel_launch(void* const* d_in, const int* in_sizes, int n_in,
                              void* d_out, int out_size)
{
    (void)in_sizes; (void)n_in; (void)out_size;
    const float* x   = (const float*)d_in[0];
    const float* sk  = (const float*)d_in[1];
    const float* Wk  = (const float*)d_in[2];
    const float* bk  = (const float*)d_in[3];
    const float* Wq  = (const float*)d_in[4];
    const float* bq  = (const float*)d_in[5];
    const float* Wv  = (const float*)d_in[6];
    const float* bv  = (const float*)d_in[7];
    const float* sc  = (const float*)d_in[8];
    const float* lng = (const float*)d_in[9];
    const float* lnb = (const float*)d_in[10];
    const float* Wo  = (const float*)d_in[11];
    const float* bo  = (const float*)d_in[12];
    float* out = (float*)d_out;

    float *vp,*retp,*lnp,*wwp,*rwp,*Pp,*cp;
    cudaGetSymbolAddress((void**)&vp,  g_v);
    cudaGetSymbolAddress((void**)&retp,g_ret);
    cudaGetSymbolAddress((void**)&lnp, g_ln);
    cudaGetSymbolAddress((void**)&wwp, g_ww);
    cudaGetSymbolAddress((void**)&rwp, g_rw);
    cudaGetSymbolAddress((void**)&Pp,  g_P);
    cudaGetSymbolAddress((void**)&cp,  g_c);

    cudaFuncSetAttribute(gemm_fused, cudaFuncAttributeMaxDynamicSharedMemorySize, GSMEM);
    cudaFuncSetAttribute(chunk_attn_mma, cudaFuncAttributeMaxDynamicSharedMemorySize, CSMEM);

    prep_kernel<<<DIMC + 1, 128>>>(Wk, bk, Wq, bq, sk, Pp, cp);

    // V projection + fused logits/softmax (block x==4)
    dim3 gv(5, NTOK/TBM);
    gemm_fused<<<gv, 256, GSMEM>>>(x, Wv, bv, nullptr, vp,
                                   Pp, cp, sc, wwp, rwp, NTOK, DIMC, 4);

    chunk_attn_mma<<<NCHUNK, 256, CSMEM>>>(rwp, wwp, vp, retp);

    ln_kernel<<<NTOK, 128>>>(retp, lng, lnb, lnp);

    // output projection + residual
    dim3 go(4, NTOK/TBM);
    gemm_fused<<<go, 256, GSMEM>>>(lnp, Wo, bo, x, out,
                                   nullptr, nullptr, nullptr, nullptr, nullptr,
                                   NTOK, DIMC, 4);
}